// round 2
// baseline (speedup 1.0000x reference)
#include <cuda_runtime.h>
#include <math.h>

#define N_ATOM  50000
#define M_NBR   12
#define N_ROW   600000
#define OFD     92
#define FDIM    64
#define EDIMM   41
#define NC_L    210
#define NC_H    256
#define UVS_L   420
#define UVS_H   512

// ---------------- scratch (device globals; no runtime allocation) ----------------
__device__ float  g_Y[(size_t)N_ROW * NC_H];      // 614.4 MB pre-activations
__device__ float  g_G[(size_t)N_ROW * EDIMM];     // edge gate values
__device__ float  g_EDGE[(size_t)N_ROW * EDIMM];  // current edge features
__device__ float  g_NODE[N_ATOM * FDIM];          // current node features
__device__ float  g_AGGR[N_ATOM * FDIM];
__device__ float  g_UV[(size_t)N_ATOM * UVS_H];   // packed self/nbr partial products
__device__ float  g_WP[FDIM * UVS_H];             // packed UV weights
__device__ float  g_BP[UVS_H];                    // packed bias
__device__ float  g_EW[EDIMM * NC_H];             // packed edge-part weights
__device__ float  g_DIST[N_ROW];
__device__ double g_S[2 * NC_H];
__device__ double g_SA[2 * FDIM];
__device__ double g_SG[2 * EDIMM];
__device__ float  g_MEAN[NC_H], g_ISTD[NC_H];
__device__ float  g_MEANA[FDIM], g_ISTDA[FDIM];
__device__ float  g_MEANG[EDIMM], g_ISTDG[EDIMM];

__device__ __forceinline__ float lrelu(float x){ return x > 0.f ? x : 0.01f*x; }
__device__ __forceinline__ float sigm(float x){ return 1.f/(1.f + __expf(-x)); }
__device__ __forceinline__ float softplus(float x){ return fmaxf(x,0.f) + log1pf(__expf(-fabsf(x))); }

// ---------------- distance ----------------
__global__ void k_dist(const float* __restrict__ nbr, const float* __restrict__ pos,
                       const float* __restrict__ cells, const int* __restrict__ eidx)
{
    int r = blockIdx.x*blockDim.x + threadIdx.x;
    if (r >= N_ROW) return;
    int n = r / M_NBR;
    float o0=nbr[r*3], o1=nbr[r*3+1], o2=nbr[r*3+2];
    const float* c = cells + (size_t)n*9;
    int g = eidx[r];
    float dd = 1e-12f;
    #pragma unroll
    for (int j=0;j<3;j++){
        float off = o0*c[j] + o1*c[3+j] + o2*c[6+j];
        float d = pos[g*3+j] + off - pos[n*3+j];
        dd += d*d;
    }
    g_DIST[r] = sqrtf(dd);
}

// ---------------- generic SIMT GEMM: C = A(Nrows x K) @ B(K x Ncols) + bias ----------------
// useGlobals=0: A,B,bias from args, C = g_NODE (embedding)
// useGlobals=1: A=g_NODE, B=g_WP, bias=g_BP, C=g_UV
__global__ void __launch_bounds__(256) k_gemm(const float* __restrict__ Ax,
                                              const float* __restrict__ Bx,
                                              const float* __restrict__ biasx,
                                              int useGlobals, int Nrows, int K, int Ncols)
{
    const float* A    = useGlobals ? g_NODE : Ax;
    const float* B    = useGlobals ? g_WP   : Bx;
    const float* bias = useGlobals ? g_BP   : biasx;
    float* C          = useGlobals ? g_UV   : g_NODE;

    __shared__ float As[64*32];
    __shared__ float Bs[32*128];
    int tid = threadIdx.x;
    int colT = tid & 31, rowT = tid >> 5;
    int r0 = blockIdx.x*64, c0 = blockIdx.y*128;
    float acc[8][4];
    #pragma unroll
    for (int ri=0;ri<8;ri++)
        #pragma unroll
        for (int ci=0;ci<4;ci++) acc[ri][ci]=0.f;

    for (int k0=0;k0<K;k0+=32){
        for (int i=tid;i<64*32;i+=256){
            int rr=i>>5, kk=i&31; int gr=r0+rr, gk=k0+kk;
            As[i] = (gr<Nrows && gk<K)? A[(size_t)gr*K+gk] : 0.f;
        }
        for (int i=tid;i<32*128;i+=256){
            int kk=i>>7, jj=i&127; int gk=k0+kk, gj=c0+jj;
            Bs[i] = (gk<K && gj<Ncols)? B[(size_t)gk*Ncols+gj] : 0.f;
        }
        __syncthreads();
        #pragma unroll 4
        for (int kk=0;kk<32;kk++){
            float a[8];
            #pragma unroll
            for (int ri=0;ri<8;ri++) a[ri]=As[(rowT+8*ri)*32+kk];
            #pragma unroll
            for (int ci=0;ci<4;ci++){
                float b=Bs[kk*128 + colT + 32*ci];
                #pragma unroll
                for (int ri=0;ri<8;ri++) acc[ri][ci] = fmaf(a[ri], b, acc[ri][ci]);
            }
        }
        __syncthreads();
    }
    #pragma unroll
    for (int ri=0;ri<8;ri++){
        int gr=r0+rowT+8*ri;
        if (gr >= Nrows) continue;
        #pragma unroll
        for (int ci=0;ci<4;ci++){
            int gj=c0+colT+32*ci;
            if (gj < Ncols) C[(size_t)gr*Ncols+gj] = acc[ri][ci] + bias[gj];
        }
    }
}

// ---------------- weight packing ----------------
__global__ void k_pack_layer(const float* __restrict__ Wn, const float* __restrict__ bn,
                             const float* __restrict__ We, const float* __restrict__ be)
{
    int stride = gridDim.x*blockDim.x;
    int t0 = blockIdx.x*blockDim.x + threadIdx.x;
    for (int idx=t0; idx<FDIM*UVS_L; idx+=stride){
        int k = idx / UVS_L, j = idx % UVS_L;
        float v;
        if (j<128)       v = Wn[k*128 + j];
        else if (j<256)  v = Wn[(64+k)*128 + (j-128)];
        else if (j<338)  v = We[k*82 + (j-256)];
        else             v = We[(64+k)*82 + (j-338)];
        g_WP[idx] = v;
    }
    for (int j=t0;j<UVS_L;j+=stride){
        float v = 0.f;
        if (j<128) v = bn[j];
        else if (j>=256 && j<338) v = be[j-256];
        g_BP[j]=v;
    }
    for (int idx=t0;idx<EDIMM*NC_L;idx+=stride){
        int k=idx/NC_L, j=idx%NC_L;
        g_EW[idx] = (j<128)? Wn[(128+k)*128 + j] : We[(128+k)*82 + (j-128)];
    }
}

__global__ void k_pack_head(const float* __restrict__ Wd, const float* __restrict__ bd,
                            const float* __restrict__ Wc, const float* __restrict__ bc)
{
    int stride = gridDim.x*blockDim.x;
    int t0 = blockIdx.x*blockDim.x + threadIdx.x;
    for (int idx=t0; idx<FDIM*UVS_H; idx+=stride){
        int k = idx / UVS_H, j = idx % UVS_H;
        float v;
        if (j<128)       v = Wd[k*128 + j];
        else if (j<256)  v = Wd[(64+k)*128 + (j-128)];
        else if (j<384)  v = Wc[k*128 + (j-256)];
        else             v = Wc[(64+k)*128 + (j-384)];
        g_WP[idx] = v;
    }
    for (int j=t0;j<UVS_H;j+=stride){
        float v = 0.f;
        if (j<128) v = bd[j];
        else if (j>=256 && j<384) v = bc[j-256];
        g_BP[j]=v;
    }
    for (int idx=t0;idx<EDIMM*NC_H;idx+=stride){
        int k=idx/NC_H, j=idx%NC_H;
        g_EW[idx] = (j<128)? Wd[(128+k)*128 + j] : Wc[(128+k)*128 + (j-128)];
    }
}

__global__ void k_zero_stats()
{
    int t = blockIdx.x*blockDim.x + threadIdx.x;
    if (t < 2*NC_H)  g_S[t]=0.0;
    if (t < 2*FDIM)  g_SA[t]=0.0;
    if (t < 2*EDIMM) g_SG[t]=0.0;
}

// ---------------- pass1: Y = edge@EW + U[n] + V[g]; accumulate channel stats ----------------
template<int NC, int CPT>
__global__ void __launch_bounds__(256) k_pass1(const float* __restrict__ Ein, int useG,
                                               const int* __restrict__ eidx, int uvS)
{
    __shared__ float sEW[EDIMM*NC + 64];
    __shared__ float sE[40*EDIMM];
    const float* E = useG ? g_EDGE : Ein;
    int tid = threadIdx.x;
    int colT = tid & 31, rowT = tid >> 5;
    for (int i=tid; i<EDIMM*NC; i+=256) sEW[i] = g_EW[i];
    float s1[CPT], s2[CPT];
    #pragma unroll
    for (int ci=0;ci<CPT;ci++){ s1[ci]=0.f; s2[ci]=0.f; }
    const int nTiles = N_ROW / 40;
    for (int t = blockIdx.x; t < nTiles; t += gridDim.x){
        int r0 = t*40;
        __syncthreads();
        for (int i=tid;i<40*EDIMM;i+=256) sE[i] = E[(size_t)r0*EDIMM + i];
        __syncthreads();
        float acc[5][CPT];
        #pragma unroll
        for (int ri=0;ri<5;ri++)
            #pragma unroll
            for (int ci=0;ci<CPT;ci++) acc[ri][ci]=0.f;
        #pragma unroll 2
        for (int k=0;k<EDIMM;k++){
            float ev[5];
            #pragma unroll
            for (int ri=0;ri<5;ri++) ev[ri] = sE[(rowT*5+ri)*EDIMM + k];
            #pragma unroll
            for (int ci=0;ci<CPT;ci++){
                float w = sEW[k*NC + colT + 32*ci];
                #pragma unroll
                for (int ri=0;ri<5;ri++) acc[ri][ci] = fmaf(ev[ri], w, acc[ri][ci]);
            }
        }
        #pragma unroll
        for (int ri=0;ri<5;ri++){
            int row = r0 + rowT*5 + ri;
            int n  = row / M_NBR;
            int gg = eidx[row];
            const float* Un = g_UV + (size_t)n*uvS;
            const float* Vg = g_UV + (size_t)gg*uvS;
            #pragma unroll
            for (int ci=0;ci<CPT;ci++){
                int j = colT + 32*ci;
                if (j < NC){
                    int uc = (j<128)? j       : j+128;
                    int vc = (j<128)? (j+128) : j+NC;
                    float y = acc[ri][ci] + Un[uc] + Vg[vc];
                    g_Y[(size_t)row*NC + j] = y;
                    s1[ci] += y;
                    s2[ci] += y*y;
                }
            }
        }
    }
    __syncthreads();
    float* red = sE;
    for (int ci=0;ci<CPT;ci++){
        red[tid] = s1[ci]; __syncthreads();
        if (tid<128) red[tid]+=red[tid+128]; __syncthreads();
        if (tid<64)  red[tid]+=red[tid+64];  __syncthreads();
        if (tid<32){
            float v = red[tid] + red[tid+32];
            int j = tid + 32*ci;
            if (j < NC) atomicAdd(&g_S[j], (double)v);
        }
        __syncthreads();
        red[tid] = s2[ci]; __syncthreads();
        if (tid<128) red[tid]+=red[tid+128]; __syncthreads();
        if (tid<64)  red[tid]+=red[tid+64];  __syncthreads();
        if (tid<32){
            float v = red[tid] + red[tid+32];
            int j = tid + 32*ci;
            if (j < NC) atomicAdd(&g_S[NC + j], (double)v);
        }
        __syncthreads();
    }
}

// ---------------- finalize stats: mean / inv_std ----------------
__global__ void k_finalize(int mode, int C, double invCnt)
{
    int t = threadIdx.x + blockIdx.x*blockDim.x;
    if (t >= C) return;
    const double* S; float* mean; float* istd;
    if (mode==0){ S=g_S;  mean=g_MEAN;  istd=g_ISTD;  }
    else if (mode==1){ S=g_SA; mean=g_MEANA; istd=g_ISTDA; }
    else { S=g_SG; mean=g_MEANG; istd=g_ISTDG; }
    double m = S[t]*invCnt;
    double v = S[C+t]*invCnt - m*m;
    mean[t] = (float)m;
    istd[t] = rsqrtf((float)v + 1e-5f);
}

// ---------------- pass2 (layer): BN + gates, M-reduction, write aggr & g, next-BN stats ----------------
__global__ void __launch_bounds__(128) k_pass2_layer()
{
    int t = threadIdx.x;
    bool isNode = t < 64;
    bool isEdge = (t >= 64 && t < 105);
    float m1=0.f,i1=0.f,m2=0.f,i2=0.f;
    int c = 0;
    if (isNode){ c=t;    m1=g_MEAN[c];     i1=g_ISTD[c];     m2=g_MEAN[64+c];  i2=g_ISTD[64+c]; }
    else if (isEdge){ c=t-64; m1=g_MEAN[128+c]; i1=g_ISTD[128+c]; m2=g_MEAN[169+c]; i2=g_ISTD[169+c]; }
    float st1=0.f, st2=0.f;
    for (int n = blockIdx.x; n < N_ATOM; n += gridDim.x){
        if (isNode){
            float a = 0.f;
            #pragma unroll
            for (int m=0;m<M_NBR;m++){
                size_t row = (size_t)(n*M_NBR+m);
                float y1 = (g_Y[row*NC_L + c]      - m1)*i1;
                float y2 = (g_Y[row*NC_L + 64 + c] - m2)*i2;
                a += sigm(y1)*lrelu(y2);
            }
            g_AGGR[n*64 + c] = a;
            st1 += a; st2 += a*a;
        } else if (isEdge){
            #pragma unroll
            for (int m=0;m<M_NBR;m++){
                size_t row = (size_t)(n*M_NBR+m);
                float y1 = (g_Y[row*NC_L + 128 + c] - m1)*i1;
                float y2 = (g_Y[row*NC_L + 169 + c] - m2)*i2;
                float gv = sigm(y1)*lrelu(y2);
                g_G[row*EDIMM + c] = gv;
                st1 += gv; st2 += gv*gv;
            }
        }
    }
    if (isNode){ atomicAdd(&g_SA[c], (double)st1); atomicAdd(&g_SA[64+c], (double)st2); }
    else if (isEdge){ atomicAdd(&g_SG[c], (double)st1); atomicAdd(&g_SG[41+c], (double)st2); }
}

__global__ void k_node_update()
{
    int idx = blockIdx.x*blockDim.x + threadIdx.x;
    if (idx >= N_ATOM*FDIM) return;
    int c = idx & 63;
    float v = g_NODE[idx] + (g_AGGR[idx] - g_MEANA[c]) * g_ISTDA[c];
    g_NODE[idx] = lrelu(v);
}

__global__ void k_edge_update(const float* __restrict__ Ein, int useG)
{
    size_t idx = (size_t)blockIdx.x*blockDim.x + threadIdx.x;
    if (idx >= (size_t)N_ROW*EDIMM) return;
    int c = (int)(idx % EDIMM);
    float e = useG ? g_EDGE[idx] : Ein[idx];
    float v = e + (g_G[idx] - g_MEANG[c]) * g_ISTDG[c];
    g_EDGE[idx] = lrelu(v);
}

// ---------------- pass2 (head): BN + softplus + channel means -> output ----------------
__global__ void __launch_bounds__(256) k_pass2_head(float* __restrict__ out)
{
    int warp = threadIdx.x >> 5, lane = threadIdx.x & 31;
    size_t r = (size_t)blockIdx.x*8 + warp;
    if (r >= N_ROW) return;
    float dist = g_DIST[r];
    float bd = 0.f, bc = 0.f;
    const float* y = g_Y + r*NC_H;
    #pragma unroll
    for (int i=0;i<8;i++){
        int cidx = lane + 32*i;
        float v = (y[cidx] - g_MEAN[cidx]) * g_ISTD[cidx];
        if (i < 4) bd += softplus(v + dist);
        else       bc += softplus(v);
    }
    #pragma unroll
    for (int o=16;o>0;o>>=1){
        bd += __shfl_down_sync(0xffffffffu, bd, o);
        bc += __shfl_down_sync(0xffffffffu, bc, o);
    }
    if (lane==0){
        out[r*2]   = bd * (1.f/128.f);
        out[r*2+1] = bc * (1.f/128.f) * (1.f/(float)N_ATOM);
    }
}

// ---------------- host orchestration ----------------
extern "C" void kernel_launch(void* const* d_in, const int* in_sizes, int n_in,
                              void* d_out, int out_size)
{
    const float* node_fea = (const float*)d_in[0];
    const float* edge_fea = (const float*)d_in[1];
    const float* nbr_off  = (const float*)d_in[2];
    const float* atom_pos = (const float*)d_in[3];
    const float* cells    = (const float*)d_in[4];
    const int*   eidx     = (const int*)  d_in[5];
    const float* W_emb = (const float*)d_in[6];
    const float* b_emb = (const float*)d_in[7];
    const float* W_pn  = (const float*)d_in[8];
    const float* b_pn  = (const float*)d_in[9];
    const float* W_pe  = (const float*)d_in[10];
    const float* b_pe  = (const float*)d_in[11];
    const float* W_d   = (const float*)d_in[12];
    const float* b_d   = (const float*)d_in[13];
    const float* W_c   = (const float*)d_in[14];
    const float* b_c   = (const float*)d_in[15];
    float* out = (float*)d_out;

    k_dist<<<(N_ROW+255)/256, 256>>>(nbr_off, atom_pos, cells, eidx);
    // embedding: node = node_fea @ W_emb + b_emb
    k_gemm<<<dim3((N_ATOM+63)/64, 1), 256>>>(node_fea, W_emb, b_emb, 0, N_ATOM, OFD, FDIM);

    for (int l=0;l<3;l++){
        int useG = (l>0) ? 1 : 0;
        k_pack_layer<<<64,256>>>(W_pn + (size_t)l*169*128, b_pn + l*128,
                                 W_pe + (size_t)l*169*82,  b_pe + l*82);
        k_gemm<<<dim3((N_ATOM+63)/64, (UVS_L+127)/128), 256>>>(nullptr,nullptr,nullptr, 1, N_ATOM, FDIM, UVS_L);
        k_zero_stats<<<2,256>>>();
        k_pass1<NC_L,7><<<1184,256>>>(edge_fea, useG, eidx, UVS_L);
        k_finalize<<<1,256>>>(0, NC_L, 1.0/(double)N_ROW);
        k_pass2_layer<<<2368,128>>>();
        k_finalize<<<1,256>>>(1, FDIM,  1.0/(double)N_ATOM);
        k_finalize<<<1,256>>>(2, EDIMM, 1.0/(double)N_ROW);
        k_node_update<<<(N_ATOM*FDIM+255)/256,256>>>();
        k_edge_update<<<(int)(((size_t)N_ROW*EDIMM+255)/256),256>>>(edge_fea, useG);
    }

    k_pack_head<<<64,256>>>(W_d, b_d, W_c, b_c);
    k_gemm<<<dim3((N_ATOM+63)/64, (UVS_H+127)/128), 256>>>(nullptr,nullptr,nullptr, 1, N_ATOM, FDIM, UVS_H);
    k_zero_stats<<<2,256>>>();
    k_pass1<NC_H,8><<<1184,256>>>(nullptr, 1, eidx, UVS_H);
    k_finalize<<<1,256>>>(0, NC_H, 1.0/(double)N_ROW);
    k_pass2_head<<<(int)((N_ROW+7)/8), 256>>>(out);
}